// round 1
// baseline (speedup 1.0000x reference)
#include <cuda_runtime.h>
#include <math.h>

#define SEQ     2048
#define DMODEL  512
#define NH      8
#define DH      64
#define BATCH   2

// Scratch (allocation-free rule: __device__ globals)
__device__ float g_Q[BATCH * NH * SEQ * DH];   // [b,h,s,dh]
__device__ float g_K[BATCH * NH * SEQ * DH];
__device__ float g_V[BATCH * NH * SEQ * DH];
__device__ float g_Z[BATCH * SEQ * DMODEL];    // [b,q,h*64+dh]

// ---------------------------------------------------------------------------
// Fused QKV projection:  C[m,n] = sum_k x[m,k] * W[n,k]
// m in [0,4096) = b*2048+s ; n in [0,1536): n<512->Q, <1024->K, else V
// Tile 128x128, BK=16, 256 threads, 8x8 per thread.
// ---------------------------------------------------------------------------
__global__ __launch_bounds__(256) void sgemm_qkv(
    const float* __restrict__ A,
    const float* __restrict__ WQ,
    const float* __restrict__ WK,
    const float* __restrict__ WV)
{
    __shared__ float As[16][128];
    __shared__ float Bs[16][128];

    const int tid = threadIdx.x;
    const int tx = tid & 15;          // n-dir
    const int ty = tid >> 4;          // m-dir
    const int r0 = tid >> 2;          // load row 0..63 (and +64)
    const int c4 = (tid & 3) << 2;    // k-offset within 16

    const int n0  = blockIdx.x * 128;   // 0..1535
    const int m0  = blockIdx.y * 128;
    const int sel = n0 >> 9;
    const int nl0 = n0 & 511;
    const float* W = (sel == 0) ? WQ : (sel == 1) ? WK : WV;
    float* Cbase   = (sel == 0) ? g_Q : (sel == 1) ? g_K : g_V;
    W += (size_t)nl0 * DMODEL;

    float acc[8][8];
#pragma unroll
    for (int i = 0; i < 8; i++)
#pragma unroll
        for (int j = 0; j < 8; j++) acc[i][j] = 0.0f;

    for (int kt = 0; kt < DMODEL; kt += 16) {
        float4 av0 = *(const float4*)&A[(size_t)(m0 + r0)      * DMODEL + kt + c4];
        float4 av1 = *(const float4*)&A[(size_t)(m0 + r0 + 64) * DMODEL + kt + c4];
        float4 bv0 = *(const float4*)&W[(size_t)(r0)           * DMODEL + kt + c4];
        float4 bv1 = *(const float4*)&W[(size_t)(r0 + 64)      * DMODEL + kt + c4];

        As[c4 + 0][r0] = av0.x; As[c4 + 1][r0] = av0.y;
        As[c4 + 2][r0] = av0.z; As[c4 + 3][r0] = av0.w;
        As[c4 + 0][r0 + 64] = av1.x; As[c4 + 1][r0 + 64] = av1.y;
        As[c4 + 2][r0 + 64] = av1.z; As[c4 + 3][r0 + 64] = av1.w;
        Bs[c4 + 0][r0] = bv0.x; Bs[c4 + 1][r0] = bv0.y;
        Bs[c4 + 2][r0] = bv0.z; Bs[c4 + 3][r0] = bv0.w;
        Bs[c4 + 0][r0 + 64] = bv1.x; Bs[c4 + 1][r0 + 64] = bv1.y;
        Bs[c4 + 2][r0 + 64] = bv1.z; Bs[c4 + 3][r0 + 64] = bv1.w;
        __syncthreads();

#pragma unroll
        for (int kk = 0; kk < 16; kk++) {
            float a[8], b[8];
            *(float4*)&a[0] = *(const float4*)&As[kk][ty * 8];
            *(float4*)&a[4] = *(const float4*)&As[kk][ty * 8 + 4];
            *(float4*)&b[0] = *(const float4*)&Bs[kk][tx * 8];
            *(float4*)&b[4] = *(const float4*)&Bs[kk][tx * 8 + 4];
#pragma unroll
            for (int i = 0; i < 8; i++)
#pragma unroll
                for (int j = 0; j < 8; j++)
                    acc[i][j] += a[i] * b[j];
        }
        __syncthreads();
    }

    // Epilogue: scatter to [b,h,s,dh]
    const int nl  = nl0 + tx * 8;
    const int h   = nl >> 6;
    const int dh0 = nl & 63;             // multiple of 8, stays within one head
    const int bI  = m0 >> 11;            // block fully inside one batch
    float* dst = Cbase + ((size_t)(bI * NH + h) * SEQ) * DH;
    const int sBase = (m0 & 2047) + ty * 8;
#pragma unroll
    for (int i = 0; i < 8; i++) {
        float* p = dst + (size_t)(sBase + i) * DH + dh0;
        *(float4*)(p)     = make_float4(acc[i][0], acc[i][1], acc[i][2], acc[i][3]);
        *(float4*)(p + 4) = make_float4(acc[i][4], acc[i][5], acc[i][6], acc[i][7]);
    }
}

// ---------------------------------------------------------------------------
// Attention collapse. Mask structure makes softmax row =
//   { -inf for p<q,  s_qq/8 at p=q,  0 for p>q }
// so z[q] = a_q * v[q] + c_q * suffix_sum_{p>q} v[p]. Exact vs reference.
// One block per (b,h), 512 threads.
// ---------------------------------------------------------------------------
__global__ __launch_bounds__(512) void attn_collapse()
{
    __shared__ float sa[SEQ];          // diag weight a_q
    __shared__ float sc[SEQ];          // off-diag weight c_q
    __shared__ float cs[8][64];        // per-chunk V sums

    const int bh = blockIdx.x;         // 0..15
    const int b = bh >> 3, h = bh & 7;
    const float* Q = g_Q + (size_t)bh * SEQ * DH;
    const float* K = g_K + (size_t)bh * SEQ * DH;
    const float* V = g_V + (size_t)bh * SEQ * DH;
    const int tid = threadIdx.x;

    // Phase 1: diagonal scores -> softmax weights
    for (int q = tid; q < SEQ; q += 512) {
        const float4* qv = (const float4*)(Q + (size_t)q * DH);
        const float4* kv = (const float4*)(K + (size_t)q * DH);
        float s = 0.0f;
#pragma unroll
        for (int i = 0; i < 16; i++) {
            float4 a = qv[i], c = kv[i];
            s += a.x * c.x + a.y * c.y + a.z * c.z + a.w * c.w;
        }
        float sd  = s * 0.125f;                 // / sqrt(64)
        int   cnt = SEQ - 1 - q;                // #positions p>q (weight exp(0))
        float m   = (cnt > 0) ? fmaxf(sd, 0.0f) : sd;
        float ed  = expf(sd - m);
        float eo  = (cnt > 0) ? expf(-m) : 0.0f;
        float Z   = ed + (float)cnt * eo;
        sa[q] = ed / Z;
        sc[q] = eo / Z;
    }
    __syncthreads();

    // Phase 2: chunk sums of V (8 chunks of 256 positions, per dh)
    const int chunk = tid >> 6;     // 0..7
    const int dh    = tid & 63;
    {
        float s = 0.0f;
        const int qe = (chunk + 1) * 256;
        for (int q = chunk * 256; q < qe; q++)
            s += V[(size_t)q * DH + dh];
        cs[chunk][dh] = s;
    }
    __syncthreads();

    // Phase 3: suffix scan within chunk, seeded by later-chunk sums
    float run = 0.0f;
    for (int c2 = chunk + 1; c2 < 8; c2++) run += cs[c2][dh];
    const int qlo = chunk * 256;
    for (int q = qlo + 255; q >= qlo; q--) {
        float v = V[(size_t)q * DH + dh];
        float z = sa[q] * v + sc[q] * run;
        g_Z[(size_t)(b * SEQ + q) * DMODEL + h * DH + dh] = z;
        run += v;
    }
}

// ---------------------------------------------------------------------------
// Output projection: out[m,d] = sum_f W_O[d,f] * z[m,f]
// ---------------------------------------------------------------------------
__global__ __launch_bounds__(256) void sgemm_out(
    const float* __restrict__ WO,
    float* __restrict__ C)
{
    __shared__ float As[16][128];
    __shared__ float Bs[16][128];

    const int tid = threadIdx.x;
    const int tx = tid & 15;
    const int ty = tid >> 4;
    const int r0 = tid >> 2;
    const int c4 = (tid & 3) << 2;

    const int n0 = blockIdx.x * 128;    // 0..511
    const int m0 = blockIdx.y * 128;
    const float* A = g_Z;
    const float* W = WO + (size_t)n0 * DMODEL;

    float acc[8][8];
#pragma unroll
    for (int i = 0; i < 8; i++)
#pragma unroll
        for (int j = 0; j < 8; j++) acc[i][j] = 0.0f;

    for (int kt = 0; kt < DMODEL; kt += 16) {
        float4 av0 = *(const float4*)&A[(size_t)(m0 + r0)      * DMODEL + kt + c4];
        float4 av1 = *(const float4*)&A[(size_t)(m0 + r0 + 64) * DMODEL + kt + c4];
        float4 bv0 = *(const float4*)&W[(size_t)(r0)           * DMODEL + kt + c4];
        float4 bv1 = *(const float4*)&W[(size_t)(r0 + 64)      * DMODEL + kt + c4];

        As[c4 + 0][r0] = av0.x; As[c4 + 1][r0] = av0.y;
        As[c4 + 2][r0] = av0.z; As[c4 + 3][r0] = av0.w;
        As[c4 + 0][r0 + 64] = av1.x; As[c4 + 1][r0 + 64] = av1.y;
        As[c4 + 2][r0 + 64] = av1.z; As[c4 + 3][r0 + 64] = av1.w;
        Bs[c4 + 0][r0] = bv0.x; Bs[c4 + 1][r0] = bv0.y;
        Bs[c4 + 2][r0] = bv0.z; Bs[c4 + 3][r0] = bv0.w;
        Bs[c4 + 0][r0 + 64] = bv1.x; Bs[c4 + 1][r0 + 64] = bv1.y;
        Bs[c4 + 2][r0 + 64] = bv1.z; Bs[c4 + 3][r0 + 64] = bv1.w;
        __syncthreads();

#pragma unroll
        for (int kk = 0; kk < 16; kk++) {
            float a[8], b[8];
            *(float4*)&a[0] = *(const float4*)&As[kk][ty * 8];
            *(float4*)&a[4] = *(const float4*)&As[kk][ty * 8 + 4];
            *(float4*)&b[0] = *(const float4*)&Bs[kk][tx * 8];
            *(float4*)&b[4] = *(const float4*)&Bs[kk][tx * 8 + 4];
#pragma unroll
            for (int i = 0; i < 8; i++)
#pragma unroll
                for (int j = 0; j < 8; j++)
                    acc[i][j] += a[i] * b[j];
        }
        __syncthreads();
    }

#pragma unroll
    for (int i = 0; i < 8; i++) {
        float* p = C + (size_t)(m0 + ty * 8 + i) * DMODEL + n0 + tx * 8;
        *(float4*)(p)     = make_float4(acc[i][0], acc[i][1], acc[i][2], acc[i][3]);
        *(float4*)(p + 4) = make_float4(acc[i][4], acc[i][5], acc[i][6], acc[i][7]);
    }
}

extern "C" void kernel_launch(void* const* d_in, const int* in_sizes, int n_in,
                              void* d_out, int out_size)
{
    const float* x  = (const float*)d_in[0];
    const float* WQ = (const float*)d_in[1];
    const float* WK = (const float*)d_in[2];
    const float* WV = (const float*)d_in[3];
    const float* WO = (const float*)d_in[4];
    float* out = (float*)d_out;

    dim3 g1(1536 / 128, (BATCH * SEQ) / 128);   // 12 x 32
    sgemm_qkv<<<g1, 256>>>(x, WQ, WK, WV);

    attn_collapse<<<BATCH * NH, 512>>>();

    dim3 g3(DMODEL / 128, (BATCH * SEQ) / 128); // 4 x 32
    sgemm_out<<<g3, 256>>>(WO, out);
}

// round 3
// speedup vs baseline: 2.0464x; 2.0464x over previous
#include <cuda_runtime.h>
#include <cuda_fp16.h>
#include <math.h>
#include <stdint.h>

#define SEQ     2048
#define DMODEL  512
#define NH      8
#define DH      64
#define BATCH   2
#define MTOT    4096

// ---------------- scratch (__device__ globals, allocation-free) -------------
__device__ __half g_xh[MTOT * DMODEL];
__device__ __half g_xl[MTOT * DMODEL];
__device__ __half g_wh[3 * DMODEL * DMODEL];   // [Wq;Wk;Wv] rows 0..1535
__device__ __half g_wl[3 * DMODEL * DMODEL];
__device__ __half g_oh[DMODEL * DMODEL];
__device__ __half g_ol[DMODEL * DMODEL];
__device__ __half g_zh[MTOT * DMODEL];
__device__ __half g_zl[MTOT * DMODEL];
__device__ float  g_Q[MTOT * DMODEL];
__device__ float  g_K[MTOT * DMODEL];
__device__ float  g_V[MTOT * DMODEL];
__device__ float  g_sa[16 * SEQ];
__device__ float  g_sc[16 * SEQ];
__device__ float  g_cs[16 * 16 * 64];

// ---------------------------------------------------------------------------
__device__ __forceinline__ uint32_t smem_u32(const void* p) {
    uint32_t a;
    asm("{ .reg .u64 t; cvta.to.shared.u64 t, %1; cvt.u32.u64 %0, t; }"
        : "=r"(a) : "l"(p));
    return a;
}

#define CPASYNC(d, s) \
    asm volatile("cp.async.cg.shared.global [%0], [%1], 16;" \
                 :: "r"(d), "l"(s) : "memory")

#define LDSM4(r, a) \
    asm volatile("ldmatrix.sync.aligned.m8n8.x4.shared.b16 {%0,%1,%2,%3}, [%4];" \
                 : "=r"((r)[0]), "=r"((r)[1]), "=r"((r)[2]), "=r"((r)[3]) \
                 : "r"(a))

#define MMA(d, a, b0, b1) \
    asm volatile("mma.sync.aligned.m16n8k16.row.col.f32.f16.f16.f32 " \
                 "{%0,%1,%2,%3},{%4,%5,%6,%7},{%8,%9},{%0,%1,%2,%3};" \
                 : "+f"((d)[0]), "+f"((d)[1]), "+f"((d)[2]), "+f"((d)[3]) \
                 : "r"((a)[0]), "r"((a)[1]), "r"((a)[2]), "r"((a)[3]), \
                   "r"(b0), "r"(b1))

// ---------------------------------------------------------------------------
// fp32 -> fp16 hi/lo conversion of x, W_Q, W_K, W_V, W_O (one shot)
// ---------------------------------------------------------------------------
__global__ __launch_bounds__(256) void convert_all(
    const float* __restrict__ x,  const float* __restrict__ wq,
    const float* __restrict__ wk, const float* __restrict__ wv,
    const float* __restrict__ wo)
{
    int t = blockIdx.x * 256 + threadIdx.x;       // float4 index, 786432 total
    const float* src;
    __half *dh, *dl;
    int idx;
    if (t < 524288)      { src = x;  dh = g_xh;            dl = g_xl;            idx = t; }
    else if (t < 589824) { src = wq; dh = g_wh;            dl = g_wl;            idx = t - 524288; }
    else if (t < 655360) { src = wk; dh = g_wh + 262144;   dl = g_wl + 262144;   idx = t - 589824; }
    else if (t < 720896) { src = wv; dh = g_wh + 524288;   dl = g_wl + 524288;   idx = t - 655360; }
    else                 { src = wo; dh = g_oh;            dl = g_ol;            idx = t - 720896; }

    float4 v = ((const float4*)src)[idx];
    __half h0 = __float2half_rn(v.x), h1 = __float2half_rn(v.y);
    __half h2 = __float2half_rn(v.z), h3 = __float2half_rn(v.w);
    __half l0 = __float2half_rn(v.x - __half2float(h0));
    __half l1 = __float2half_rn(v.y - __half2float(h1));
    __half l2 = __float2half_rn(v.z - __half2float(h2));
    __half l3 = __float2half_rn(v.w - __half2float(h3));
    __half2* ph = (__half2*)(dh + idx * 4);
    __half2* pl = (__half2*)(dl + idx * 4);
    ph[0] = __halves2half2(h0, h1); ph[1] = __halves2half2(h2, h3);
    pl[0] = __halves2half2(l0, l1); pl[1] = __halves2half2(l2, l3);
}

// ---------------------------------------------------------------------------
// HMMA fp16x3 GEMM: C[m,n] = sum_k A[m,k]*B[n,k]
// CTA 128x128, BK=64, 256 thr (8 warps: 4m x 2n, warp tile 32x64),
// cp.async double-buffer, ldmatrix, mma.sync m16n8k16.
// ---------------------------------------------------------------------------
#define SROW 72                       // padded row in halves (144 B)
#define MATS (128 * SROW)             // halves per matrix tile
#define BUFH (4 * MATS)               // halves per buffer (Ah,Al,Bh,Bl)
#define GEMM_SMEM (2 * BUFH * 2)      // bytes

__global__ __launch_bounds__(256, 1) void gemm_mma(
    const __half* __restrict__ Ah, const __half* __restrict__ Al,
    const __half* __restrict__ Bh, const __half* __restrict__ Bl,
    float* __restrict__ C0, float* __restrict__ C1, float* __restrict__ C2)
{
    extern __shared__ __half sm[];
    const uint32_t sb = smem_u32(sm);
    const int tid = threadIdx.x;
    const int lane = tid & 31, wid = tid >> 5;
    const int wm = wid & 3, wn = wid >> 2;
    const int n0 = blockIdx.x * 128, m0 = blockIdx.y * 128;
    float* C = (n0 < 512) ? C0 : (n0 < 1024) ? C1 : C2;
    const int ncol0 = n0 & 511;

    // cp.async assignment: row = tid>>1, half-row (32 halves) = tid&1
    const int lr = tid >> 1, lp = tid & 1;
    const __half* gAh = Ah + (size_t)(m0 + lr) * 512 + lp * 32;
    const __half* gAl = Al + (size_t)(m0 + lr) * 512 + lp * 32;
    const __half* gBh = Bh + (size_t)(n0 + lr) * 512 + lp * 32;
    const __half* gBl = Bl + (size_t)(n0 + lr) * 512 + lp * 32;
    const uint32_t dst0 = sb + (uint32_t)(lr * SROW + lp * 32) * 2;

#define LOADCHUNK(c, b) { \
        const uint32_t d = dst0 + (uint32_t)(b) * (BUFH * 2); \
        const int ko = (c) * 64; \
        _Pragma("unroll") \
        for (int j = 0; j < 4; j++) { \
            CPASYNC(d + 0 * MATS * 2 + j * 16, gAh + ko + j * 8); \
            CPASYNC(d + 1 * MATS * 2 + j * 16, gAl + ko + j * 8); \
            CPASYNC(d + 2 * MATS * 2 + j * 16, gBh + ko + j * 8); \
            CPASYNC(d + 3 * MATS * 2 + j * 16, gBl + ko + j * 8); \
        } }

    float acc[2][8][4];
#pragma unroll
    for (int i = 0; i < 2; i++)
#pragma unroll
        for (int j = 0; j < 8; j++)
#pragma unroll
            for (int k = 0; k < 4; k++) acc[i][j][k] = 0.0f;

    LOADCHUNK(0, 0);
    asm volatile("cp.async.commit_group;" ::: "memory");

    // precomputed fragment address pieces
    const uint32_t a_row_off =
        (uint32_t)((wm * 32 + (lane & 15)) * SROW) * 2 + (uint32_t)((lane >> 4) * 16);
    const int bn = wn * 64 + (lane & 7) + ((lane >> 4) << 3);
    const uint32_t b_row_off =
        (uint32_t)(bn * SROW) * 2 + (uint32_t)(((lane >> 3) & 1) * 16);

    for (int c = 0; c < 8; c++) {
        if (c < 7) {
            LOADCHUNK(c + 1, (c + 1) & 1);
            asm volatile("cp.async.commit_group;" ::: "memory");
            asm volatile("cp.async.wait_group 1;" ::: "memory");
        } else {
            asm volatile("cp.async.wait_group 0;" ::: "memory");
        }
        __syncthreads();

        const uint32_t base = sb + (uint32_t)(c & 1) * (BUFH * 2);
#pragma unroll
        for (int kk = 0; kk < 4; kk++) {
            const uint32_t aH = base + a_row_off + kk * 32;
            const uint32_t aL = aH + MATS * 2;
            uint32_t ah0[4], ah1[4], al0[4], al1[4];
            LDSM4(ah0, aH);
            LDSM4(ah1, aH + 16 * SROW * 2);
            LDSM4(al0, aL);
            LDSM4(al1, aL + 16 * SROW * 2);

            const uint32_t bH = base + 2 * MATS * 2 + b_row_off + kk * 32;
            const uint32_t bL = bH + MATS * 2;
#pragma unroll
            for (int jp = 0; jp < 4; jp++) {
                uint32_t bh[4], bl[4];
                LDSM4(bh, bH + jp * 16 * SROW * 2);
                LDSM4(bl, bL + jp * 16 * SROW * 2);
                MMA(acc[0][2 * jp],     ah0, bh[0], bh[1]);
                MMA(acc[0][2 * jp],     ah0, bl[0], bl[1]);
                MMA(acc[0][2 * jp],     al0, bh[0], bh[1]);
                MMA(acc[1][2 * jp],     ah1, bh[0], bh[1]);
                MMA(acc[1][2 * jp],     ah1, bl[0], bl[1]);
                MMA(acc[1][2 * jp],     al1, bh[0], bh[1]);
                MMA(acc[0][2 * jp + 1], ah0, bh[2], bh[3]);
                MMA(acc[0][2 * jp + 1], ah0, bl[2], bl[3]);
                MMA(acc[0][2 * jp + 1], al0, bh[2], bh[3]);
                MMA(acc[1][2 * jp + 1], ah1, bh[2], bh[3]);
                MMA(acc[1][2 * jp + 1], ah1, bl[2], bl[3]);
                MMA(acc[1][2 * jp + 1], al1, bh[2], bh[3]);
            }
        }
        __syncthreads();
    }

    // Epilogue
    const int r0 = m0 + wm * 32 + (lane >> 2);
    const int cb = ncol0 + wn * 64 + (lane & 3) * 2;
#pragma unroll
    for (int mi = 0; mi < 2; mi++) {
        const int r = r0 + mi * 16;
#pragma unroll
        for (int ni = 0; ni < 8; ni++) {
            const int cg = cb + ni * 8;
            *(float2*)&C[(size_t)r * 512 + cg] =
                make_float2(acc[mi][ni][0], acc[mi][ni][1]);
            *(float2*)&C[(size_t)(r + 8) * 512 + cg] =
                make_float2(acc[mi][ni][2], acc[mi][ni][3]);
        }
    }
}

// ---------------------------------------------------------------------------
// Collapse: masked softmax row = {-inf p<q, s_qq/8 at p=q, 0 p>q}
//   => z[q] = a_q*v[q] + c_q*suffix_{p>q} v[p]   (exact)
// ---------------------------------------------------------------------------
__global__ __launch_bounds__(256) void attn_stats()
{
    int t = blockIdx.x * 256 + threadIdx.x;   // 0..32767
    int m = t >> 3;
    int h = t & 7;
    const float4* qv = (const float4*)(g_Q + (size_t)m * DMODEL + h * DH);
    const float4* kv = (const float4*)(g_K + (size_t)m * DMODEL + h * DH);
    float s = 0.0f;
#pragma unroll
    for (int i = 0; i < 16; i++) {
        float4 a = qv[i], c = kv[i];
        s += a.x * c.x + a.y * c.y + a.z * c.z + a.w * c.w;
    }
    int b = m >> 11, q = m & 2047;
    float sd = s * 0.125f;
    int cnt = SEQ - 1 - q;
    float mx = (cnt > 0) ? fmaxf(sd, 0.0f) : sd;
    float ed = expf(sd - mx);
    float eo = (cnt > 0) ? expf(-mx) : 0.0f;
    float Z = ed + (float)cnt * eo;
    g_sa[(b * 8 + h) * SEQ + q] = ed / Z;
    g_sc[(b * 8 + h) * SEQ + q] = eo / Z;
}

__global__ __launch_bounds__(64) void v_chunksum()
{
    int chunk = blockIdx.x, bh = blockIdx.y;
    int b = bh >> 3, h = bh & 7, dh = threadIdx.x;
    const float* base = g_V + (size_t)(b * SEQ + chunk * 128) * DMODEL + h * DH + dh;
    float s = 0.0f;
#pragma unroll 4
    for (int i = 0; i < 128; i++) s += base[(size_t)i * DMODEL];
    g_cs[(bh * 16 + chunk) * 64 + dh] = s;
}

__global__ __launch_bounds__(64) void v_scan()
{
    int chunk = blockIdx.x, bh = blockIdx.y;
    int b = bh >> 3, h = bh & 7, dh = threadIdx.x;
    float run = 0.0f;
    for (int c2 = chunk + 1; c2 < 16; c2++)
        run += g_cs[(bh * 16 + c2) * 64 + dh];
    for (int i = 127; i >= 0; i--) {
        int q = chunk * 128 + i;
        size_t row = (size_t)(b * SEQ + q) * DMODEL + h * DH + dh;
        float v = g_V[row];
        float z = g_sa[bh * SEQ + q] * v + g_sc[bh * SEQ + q] * run;
        __half zh = __float2half_rn(z);
        g_zh[row] = zh;
        g_zl[row] = __float2half_rn(z - __half2float(zh));
        run += v;
    }
}

// ---------------------------------------------------------------------------
extern "C" void kernel_launch(void* const* d_in, const int* in_sizes, int n_in,
                              void* d_out, int out_size)
{
    const float* x  = (const float*)d_in[0];
    const float* WQ = (const float*)d_in[1];
    const float* WK = (const float*)d_in[2];
    const float* WV = (const float*)d_in[3];
    const float* WO = (const float*)d_in[4];
    float* out = (float*)d_out;

    cudaFuncSetAttribute(gemm_mma, cudaFuncAttributeMaxDynamicSharedMemorySize,
                         GEMM_SMEM);

    __half *xh, *xl, *wh, *wl, *oh, *ol, *zh, *zl;
    float *gq, *gk, *gv;
    cudaGetSymbolAddress((void**)&xh, g_xh);
    cudaGetSymbolAddress((void**)&xl, g_xl);
    cudaGetSymbolAddress((void**)&wh, g_wh);
    cudaGetSymbolAddress((void**)&wl, g_wl);
    cudaGetSymbolAddress((void**)&oh, g_oh);
    cudaGetSymbolAddress((void**)&ol, g_ol);
    cudaGetSymbolAddress((void**)&zh, g_zh);
    cudaGetSymbolAddress((void**)&zl, g_zl);
    cudaGetSymbolAddress((void**)&gq, g_Q);
    cudaGetSymbolAddress((void**)&gk, g_K);
    cudaGetSymbolAddress((void**)&gv, g_V);

    convert_all<<<3072, 256>>>(x, WQ, WK, WV, WO);

    dim3 gqkv(12, 32);   // N=1536 fused, M=4096
    gemm_mma<<<gqkv, 256, GEMM_SMEM>>>(xh, xl, wh, wl, gq, gk, gv);

    attn_stats<<<128, 256>>>();
    v_chunksum<<<dim3(16, 16), 64>>>();
    v_scan<<<dim3(16, 16), 64>>>();

    dim3 gout(4, 32);    // N=512
    gemm_mma<<<gout, 256, GEMM_SMEM>>>(zh, zl, oh, ol, out, out, out);
}

// round 4
// speedup vs baseline: 2.4424x; 1.1935x over previous
#include <cuda_runtime.h>
#include <cuda_fp16.h>
#include <math.h>
#include <stdint.h>

#define SEQ     2048
#define DMODEL  512
#define NH      8
#define DH      64
#define BATCH   2
#define MTOT    4096

// ---------------- scratch (__device__ globals, allocation-free) -------------
__device__ __half g_xh[MTOT * DMODEL];
__device__ __half g_xl[MTOT * DMODEL];
__device__ __half g_wh[3 * DMODEL * DMODEL];   // [Wq;Wk;Wv] rows 0..1535
__device__ __half g_wl[3 * DMODEL * DMODEL];
__device__ __half g_oh[DMODEL * DMODEL];
__device__ __half g_ol[DMODEL * DMODEL];
__device__ __half g_zh[MTOT * DMODEL];
__device__ __half g_zl[MTOT * DMODEL];
__device__ float  g_Q[MTOT * DMODEL];
__device__ float  g_K[MTOT * DMODEL];
__device__ float  g_V[MTOT * DMODEL];
__device__ float  g_sa[16 * SEQ];
__device__ float  g_sc[16 * SEQ];
__device__ float  g_cs[16 * 64 * 64];   // per-(bh, chunk32, dh) V column sums

// ---------------------------------------------------------------------------
__device__ __forceinline__ uint32_t smem_u32(const void* p) {
    uint32_t a;
    asm("{ .reg .u64 t; cvta.to.shared.u64 t, %1; cvt.u32.u64 %0, t; }"
        : "=r"(a) : "l"(p));
    return a;
}

#define CPASYNC(d, s) \
    asm volatile("cp.async.cg.shared.global [%0], [%1], 16;" \
                 :: "r"(d), "l"(s) : "memory")

#define LDSM4(r, a) \
    asm volatile("ldmatrix.sync.aligned.m8n8.x4.shared.b16 {%0,%1,%2,%3}, [%4];" \
                 : "=r"((r)[0]), "=r"((r)[1]), "=r"((r)[2]), "=r"((r)[3]) \
                 : "r"(a))

#define MMA(d, a, b0, b1) \
    asm volatile("mma.sync.aligned.m16n8k16.row.col.f32.f16.f16.f32 " \
                 "{%0,%1,%2,%3},{%4,%5,%6,%7},{%8,%9},{%0,%1,%2,%3};" \
                 : "+f"((d)[0]), "+f"((d)[1]), "+f"((d)[2]), "+f"((d)[3]) \
                 : "r"((a)[0]), "r"((a)[1]), "r"((a)[2]), "r"((a)[3]), \
                   "r"(b0), "r"(b1))

// ---------------------------------------------------------------------------
// fp32 -> fp16 hi/lo conversion of x, W_Q, W_K, W_V, W_O (one shot)
// ---------------------------------------------------------------------------
__global__ __launch_bounds__(256) void convert_all(
    const float* __restrict__ x,  const float* __restrict__ wq,
    const float* __restrict__ wk, const float* __restrict__ wv,
    const float* __restrict__ wo)
{
    int t = blockIdx.x * 256 + threadIdx.x;       // float4 index, 786432 total
    const float* src;
    __half *dh, *dl;
    int idx;
    if (t < 524288)      { src = x;  dh = g_xh;            dl = g_xl;            idx = t; }
    else if (t < 589824) { src = wq; dh = g_wh;            dl = g_wl;            idx = t - 524288; }
    else if (t < 655360) { src = wk; dh = g_wh + 262144;   dl = g_wl + 262144;   idx = t - 589824; }
    else if (t < 720896) { src = wv; dh = g_wh + 524288;   dl = g_wl + 524288;   idx = t - 655360; }
    else                 { src = wo; dh = g_oh;            dl = g_ol;            idx = t - 720896; }

    float4 v = ((const float4*)src)[idx];
    __half h0 = __float2half_rn(v.x), h1 = __float2half_rn(v.y);
    __half h2 = __float2half_rn(v.z), h3 = __float2half_rn(v.w);
    __half l0 = __float2half_rn(v.x - __half2float(h0));
    __half l1 = __float2half_rn(v.y - __half2float(h1));
    __half l2 = __float2half_rn(v.z - __half2float(h2));
    __half l3 = __float2half_rn(v.w - __half2float(h3));
    __half2* ph = (__half2*)(dh + idx * 4);
    __half2* pl = (__half2*)(dl + idx * 4);
    ph[0] = __halves2half2(h0, h1); ph[1] = __halves2half2(h2, h3);
    pl[0] = __halves2half2(l0, l1); pl[1] = __halves2half2(l2, l3);
}

// ---------------------------------------------------------------------------
// HMMA fp16x3 GEMM: C[m,n] = sum_k A[m,k]*B[n,k]
// CTA 128x128, BK=64, 256 thr (8 warps: 4m x 2n, warp tile 32x64),
// cp.async double-buffer, ldmatrix, mma.sync m16n8k16.
// ---------------------------------------------------------------------------
#define SROW 72                       // padded row in halves (144 B)
#define MATS (128 * SROW)             // halves per matrix tile
#define BUFH (4 * MATS)               // halves per buffer (Ah,Al,Bh,Bl)
#define GEMM_SMEM (2 * BUFH * 2)      // bytes

__global__ __launch_bounds__(256, 1) void gemm_mma(
    const __half* __restrict__ Ah, const __half* __restrict__ Al,
    const __half* __restrict__ Bh, const __half* __restrict__ Bl,
    float* __restrict__ C0, float* __restrict__ C1, float* __restrict__ C2)
{
    extern __shared__ __half sm[];
    const uint32_t sb = smem_u32(sm);
    const int tid = threadIdx.x;
    const int lane = tid & 31, wid = tid >> 5;
    const int wm = wid & 3, wn = wid >> 2;
    const int n0 = blockIdx.x * 128, m0 = blockIdx.y * 128;
    float* C = (n0 < 512) ? C0 : (n0 < 1024) ? C1 : C2;
    const int ncol0 = n0 & 511;

    // cp.async assignment: row = tid>>1, half-row (32 halves) = tid&1
    const int lr = tid >> 1, lp = tid & 1;
    const __half* gAh = Ah + (size_t)(m0 + lr) * 512 + lp * 32;
    const __half* gAl = Al + (size_t)(m0 + lr) * 512 + lp * 32;
    const __half* gBh = Bh + (size_t)(n0 + lr) * 512 + lp * 32;
    const __half* gBl = Bl + (size_t)(n0 + lr) * 512 + lp * 32;
    const uint32_t dst0 = sb + (uint32_t)(lr * SROW + lp * 32) * 2;

#define LOADCHUNK(c, b) { \
        const uint32_t d = dst0 + (uint32_t)(b) * (BUFH * 2); \
        const int ko = (c) * 64; \
        _Pragma("unroll") \
        for (int j = 0; j < 4; j++) { \
            CPASYNC(d + 0 * MATS * 2 + j * 16, gAh + ko + j * 8); \
            CPASYNC(d + 1 * MATS * 2 + j * 16, gAl + ko + j * 8); \
            CPASYNC(d + 2 * MATS * 2 + j * 16, gBh + ko + j * 8); \
            CPASYNC(d + 3 * MATS * 2 + j * 16, gBl + ko + j * 8); \
        } }

    float acc[2][8][4];
#pragma unroll
    for (int i = 0; i < 2; i++)
#pragma unroll
        for (int j = 0; j < 8; j++)
#pragma unroll
            for (int k = 0; k < 4; k++) acc[i][j][k] = 0.0f;

    LOADCHUNK(0, 0);
    asm volatile("cp.async.commit_group;" ::: "memory");

    // precomputed fragment address pieces
    const uint32_t a_row_off =
        (uint32_t)((wm * 32 + (lane & 15)) * SROW) * 2 + (uint32_t)((lane >> 4) * 16);
    const int bn = wn * 64 + (lane & 7) + ((lane >> 4) << 3);
    const uint32_t b_row_off =
        (uint32_t)(bn * SROW) * 2 + (uint32_t)(((lane >> 3) & 1) * 16);

    for (int c = 0; c < 8; c++) {
        if (c < 7) {
            LOADCHUNK(c + 1, (c + 1) & 1);
            asm volatile("cp.async.commit_group;" ::: "memory");
            asm volatile("cp.async.wait_group 1;" ::: "memory");
        } else {
            asm volatile("cp.async.wait_group 0;" ::: "memory");
        }
        __syncthreads();

        const uint32_t base = sb + (uint32_t)(c & 1) * (BUFH * 2);
#pragma unroll
        for (int kk = 0; kk < 4; kk++) {
            const uint32_t aH = base + a_row_off + kk * 32;
            const uint32_t aL = aH + MATS * 2;
            uint32_t ah0[4], ah1[4], al0[4], al1[4];
            LDSM4(ah0, aH);
            LDSM4(ah1, aH + 16 * SROW * 2);
            LDSM4(al0, aL);
            LDSM4(al1, aL + 16 * SROW * 2);

            const uint32_t bH = base + 2 * MATS * 2 + b_row_off + kk * 32;
            const uint32_t bL = bH + MATS * 2;
#pragma unroll
            for (int jp = 0; jp < 4; jp++) {
                uint32_t bh[4], bl[4];
                LDSM4(bh, bH + jp * 16 * SROW * 2);
                LDSM4(bl, bL + jp * 16 * SROW * 2);
                MMA(acc[0][2 * jp],     ah0, bh[0], bh[1]);
                MMA(acc[0][2 * jp],     ah0, bl[0], bl[1]);
                MMA(acc[0][2 * jp],     al0, bh[0], bh[1]);
                MMA(acc[1][2 * jp],     ah1, bh[0], bh[1]);
                MMA(acc[1][2 * jp],     ah1, bl[0], bl[1]);
                MMA(acc[1][2 * jp],     al1, bh[0], bh[1]);
                MMA(acc[0][2 * jp + 1], ah0, bh[2], bh[3]);
                MMA(acc[0][2 * jp + 1], ah0, bl[2], bl[3]);
                MMA(acc[0][2 * jp + 1], al0, bh[2], bh[3]);
                MMA(acc[1][2 * jp + 1], ah1, bh[2], bh[3]);
                MMA(acc[1][2 * jp + 1], ah1, bl[2], bl[3]);
                MMA(acc[1][2 * jp + 1], al1, bh[2], bh[3]);
            }
        }
        __syncthreads();
    }

    // Epilogue
    const int r0 = m0 + wm * 32 + (lane >> 2);
    const int cb = ncol0 + wn * 64 + (lane & 3) * 2;
#pragma unroll
    for (int mi = 0; mi < 2; mi++) {
        const int r = r0 + mi * 16;
#pragma unroll
        for (int ni = 0; ni < 8; ni++) {
            const int cg = cb + ni * 8;
            *(float2*)&C[(size_t)r * 512 + cg] =
                make_float2(acc[mi][ni][0], acc[mi][ni][1]);
            *(float2*)&C[(size_t)(r + 8) * 512 + cg] =
                make_float2(acc[mi][ni][2], acc[mi][ni][3]);
        }
    }
}

// ---------------------------------------------------------------------------
// Collapse: masked softmax row = {-inf p<q, s_qq/8 at p=q, 0 p>q}
//   => z[q] = a_q*v[q] + c_q*suffix_{p>q} v[p]   (exact)
// ---------------------------------------------------------------------------
__global__ __launch_bounds__(256) void attn_stats()
{
    int t = blockIdx.x * 256 + threadIdx.x;   // 0..32767
    int m = t >> 3;
    int h = t & 7;
    const float4* qv = (const float4*)(g_Q + (size_t)m * DMODEL + h * DH);
    const float4* kv = (const float4*)(g_K + (size_t)m * DMODEL + h * DH);
    float s = 0.0f;
#pragma unroll
    for (int i = 0; i < 16; i++) {
        float4 a = qv[i], c = kv[i];
        s += a.x * c.x + a.y * c.y + a.z * c.z + a.w * c.w;
    }
    int b = m >> 11, q = m & 2047;
    float sd = s * 0.125f;
    int cnt = SEQ - 1 - q;
    float mx = (cnt > 0) ? fmaxf(sd, 0.0f) : sd;
    float ed = expf(sd - mx);
    float eo = (cnt > 0) ? expf(-mx) : 0.0f;
    float Z = ed + (float)cnt * eo;
    g_sa[(b * 8 + h) * SEQ + q] = ed / Z;
    g_sc[(b * 8 + h) * SEQ + q] = eo / Z;
}

// 64 chunks of 32 rows per (b,h). grid (16,16) x 256 thr = 65k threads.
__global__ __launch_bounds__(256) void v_chunksum()
{
    int bh = blockIdx.y;                    // 0..15
    int chunk = blockIdx.x * 4 + (threadIdx.x >> 6);  // 0..63
    int dh = threadIdx.x & 63;
    int b = bh >> 3, h = bh & 7;
    const float* base = g_V + (size_t)(b * SEQ + chunk * 32) * DMODEL + h * DH + dh;
    float s = 0.0f;
#pragma unroll 8
    for (int i = 0; i < 32; i++) s += base[(size_t)i * DMODEL];
    g_cs[(bh * 64 + chunk) * 64 + dh] = s;
}

__global__ __launch_bounds__(256) void v_scan()
{
    int bh = blockIdx.y;
    int chunk = blockIdx.x * 4 + (threadIdx.x >> 6);
    int dh = threadIdx.x & 63;
    int b = bh >> 3, h = bh & 7;

    float run = 0.0f;
    const float* cs = g_cs + (size_t)bh * 64 * 64 + dh;
    for (int c2 = chunk + 1; c2 < 64; c2++)
        run += cs[(size_t)c2 * 64];

    const float* sa = g_sa + bh * SEQ;
    const float* sc = g_sc + bh * SEQ;
    const int q0 = chunk * 32;
#pragma unroll 4
    for (int i = 31; i >= 0; i--) {
        int q = q0 + i;
        size_t row = (size_t)(b * SEQ + q) * DMODEL + h * DH + dh;
        float v = g_V[row];
        float z = sa[q] * v + sc[q] * run;
        __half zh = __float2half_rn(z);
        g_zh[row] = zh;
        g_zl[row] = __float2half_rn(z - __half2float(zh));
        run += v;
    }
}

// ---------------------------------------------------------------------------
extern "C" void kernel_launch(void* const* d_in, const int* in_sizes, int n_in,
                              void* d_out, int out_size)
{
    const float* x  = (const float*)d_in[0];
    const float* WQ = (const float*)d_in[1];
    const float* WK = (const float*)d_in[2];
    const float* WV = (const float*)d_in[3];
    const float* WO = (const float*)d_in[4];
    float* out = (float*)d_out;

    cudaFuncSetAttribute(gemm_mma, cudaFuncAttributeMaxDynamicSharedMemorySize,
                         GEMM_SMEM);

    __half *xh, *xl, *wh, *wl, *oh, *ol, *zh, *zl;
    float *gq, *gk, *gv;
    cudaGetSymbolAddress((void**)&xh, g_xh);
    cudaGetSymbolAddress((void**)&xl, g_xl);
    cudaGetSymbolAddress((void**)&wh, g_wh);
    cudaGetSymbolAddress((void**)&wl, g_wl);
    cudaGetSymbolAddress((void**)&oh, g_oh);
    cudaGetSymbolAddress((void**)&ol, g_ol);
    cudaGetSymbolAddress((void**)&zh, g_zh);
    cudaGetSymbolAddress((void**)&zl, g_zl);
    cudaGetSymbolAddress((void**)&gq, g_Q);
    cudaGetSymbolAddress((void**)&gk, g_K);
    cudaGetSymbolAddress((void**)&gv, g_V);

    convert_all<<<3072, 256>>>(x, WQ, WK, WV, WO);

    dim3 gqkv(12, 32);   // N=1536 fused, M=4096
    gemm_mma<<<gqkv, 256, GEMM_SMEM>>>(xh, xl, wh, wl, gq, gk, gv);

    attn_stats<<<128, 256>>>();
    v_chunksum<<<dim3(16, 16), 256>>>();
    v_scan<<<dim3(16, 16), 256>>>();

    dim3 gout(4, 32);    // N=512
    gemm_mma<<<gout, 256, GEMM_SMEM>>>(zh, zl, oh, ol, out, out, out);
}

// round 5
// speedup vs baseline: 2.9545x; 1.2097x over previous
#include <cuda_runtime.h>
#include <cuda_fp16.h>
#include <math.h>
#include <stdint.h>

#define SEQ     2048
#define DMODEL  512
#define NH      8
#define DH      64
#define BATCH   2
#define MTOT    4096

// ---------------- scratch (__device__ globals, allocation-free) -------------
__device__ __half g_xh[MTOT * DMODEL];
__device__ __half g_xl[MTOT * DMODEL];
__device__ __half g_wh[3 * DMODEL * DMODEL];   // [Wq;Wk;Wv] rows 0..1535
__device__ __half g_wl[3 * DMODEL * DMODEL];   // lo used only for Wv range
__device__ __half g_oh[DMODEL * DMODEL];
__device__ __half g_ol[DMODEL * DMODEL];
__device__ __half g_zh[MTOT * DMODEL];
__device__ __half g_zl[MTOT * DMODEL];
__device__ float  g_Q[MTOT * DMODEL];
__device__ float  g_K[MTOT * DMODEL];
__device__ float  g_V[MTOT * DMODEL];
__device__ float  g_sa[16 * SEQ];
__device__ float  g_sc[16 * SEQ];
__device__ float  g_cs[16 * 64 * 64];   // per-(bh, chunk32, dh) V column sums

// ---------------------------------------------------------------------------
__device__ __forceinline__ uint32_t smem_u32(const void* p) {
    uint32_t a;
    asm("{ .reg .u64 t; cvta.to.shared.u64 t, %1; cvt.u32.u64 %0, t; }"
        : "=r"(a) : "l"(p));
    return a;
}

#define CPASYNC(d, s) \
    asm volatile("cp.async.cg.shared.global [%0], [%1], 16;" \
                 :: "r"(d), "l"(s) : "memory")

#define LDSM4(r, a) \
    asm volatile("ldmatrix.sync.aligned.m8n8.x4.shared.b16 {%0,%1,%2,%3}, [%4];" \
                 : "=r"((r)[0]), "=r"((r)[1]), "=r"((r)[2]), "=r"((r)[3]) \
                 : "r"(a))

#define MMA(d, a, b0, b1) \
    asm volatile("mma.sync.aligned.m16n8k16.row.col.f32.f16.f16.f32 " \
                 "{%0,%1,%2,%3},{%4,%5,%6,%7},{%8,%9},{%0,%1,%2,%3};" \
                 : "+f"((d)[0]), "+f"((d)[1]), "+f"((d)[2]), "+f"((d)[3]) \
                 : "r"((a)[0]), "r"((a)[1]), "r"((a)[2]), "r"((a)[3]), \
                   "r"(b0), "r"(b1))

// ---------------------------------------------------------------------------
// fp32 -> fp16 hi/lo conversion (lo skipped for Wq/Wk: Q,K run plain fp16)
// ---------------------------------------------------------------------------
__global__ __launch_bounds__(256) void convert_all(
    const float* __restrict__ x,  const float* __restrict__ wq,
    const float* __restrict__ wk, const float* __restrict__ wv,
    const float* __restrict__ wo)
{
    int t = blockIdx.x * 256 + threadIdx.x;       // float4 index, 786432 total
    const float* src;
    __half *dh, *dl;
    int idx;
    bool wantLo = true;
    if (t < 524288)      { src = x;  dh = g_xh;          dl = g_xl;          idx = t; }
    else if (t < 589824) { src = wq; dh = g_wh;          dl = g_wl;          idx = t - 524288; wantLo = false; }
    else if (t < 655360) { src = wk; dh = g_wh + 262144; dl = g_wl + 262144; idx = t - 589824; wantLo = false; }
    else if (t < 720896) { src = wv; dh = g_wh + 524288; dl = g_wl + 524288; idx = t - 655360; }
    else                 { src = wo; dh = g_oh;          dl = g_ol;          idx = t - 720896; }

    float4 v = ((const float4*)src)[idx];
    __half h0 = __float2half_rn(v.x), h1 = __float2half_rn(v.y);
    __half h2 = __float2half_rn(v.z), h3 = __float2half_rn(v.w);
    __half2* ph = (__half2*)(dh + idx * 4);
    ph[0] = __halves2half2(h0, h1); ph[1] = __halves2half2(h2, h3);
    if (wantLo) {
        __half l0 = __float2half_rn(v.x - __half2float(h0));
        __half l1 = __float2half_rn(v.y - __half2float(h1));
        __half l2 = __float2half_rn(v.z - __half2float(h2));
        __half l3 = __float2half_rn(v.w - __half2float(h3));
        __half2* pl = (__half2*)(dl + idx * 4);
        pl[0] = __halves2half2(l0, l1); pl[1] = __halves2half2(l2, l3);
    }
}

// ---------------------------------------------------------------------------
// HMMA GEMM: C[m,n] = sum_k A[m,k]*B[n,k]
// SPLITS=3: fp16x3 hi/lo compensated (Ah*Bh + Ah*Bl + Al*Bh)
// SPLITS=1: plain fp16 (Ah*Bh)
// CTA 128x128, BK=64, 256 thr (8 warps: 4m x 2n), cp.async double-buffer.
// ---------------------------------------------------------------------------
#define SROW 72                       // padded row in halves (144 B)
#define MATS (128 * SROW)             // halves per matrix tile

template<int SPLITS>
__global__ __launch_bounds__(256) void gemm_mma(
    const __half* __restrict__ Ah, const __half* __restrict__ Al,
    const __half* __restrict__ Bh, const __half* __restrict__ Bl,
    float* __restrict__ C0, float* __restrict__ C1, float* __restrict__ C2)
{
    constexpr int NMAT = (SPLITS == 1) ? 2 : 4;
    constexpr int M_AH = 0;
    constexpr int M_AL = (SPLITS == 1) ? 0 : 1;
    constexpr int M_BH = (SPLITS == 1) ? 1 : 2;
    constexpr int M_BL = (SPLITS == 1) ? 1 : 3;
    constexpr uint32_t BUFB = (uint32_t)NMAT * MATS * 2;   // bytes per buffer

    extern __shared__ __half sm[];
    const uint32_t sb = smem_u32(sm);
    const int tid = threadIdx.x;
    const int lane = tid & 31, wid = tid >> 5;
    const int wm = wid & 3, wn = wid >> 2;
    const int n0 = blockIdx.x * 128, m0 = blockIdx.y * 128;
    float* C = (n0 < 512) ? C0 : (n0 < 1024) ? C1 : C2;
    const int ncol0 = n0 & 511;

    const int lr = tid >> 1, lp = tid & 1;
    const __half* gAh = Ah + (size_t)(m0 + lr) * 512 + lp * 32;
    const __half* gAl = Al + (size_t)(m0 + lr) * 512 + lp * 32;
    const __half* gBh = Bh + (size_t)(n0 + lr) * 512 + lp * 32;
    const __half* gBl = Bl + (size_t)(n0 + lr) * 512 + lp * 32;
    const uint32_t dst0 = sb + (uint32_t)(lr * SROW + lp * 32) * 2;

#define LOADCHUNK(c, b) { \
        const uint32_t d = dst0 + (uint32_t)(b) * BUFB; \
        const int ko = (c) * 64; \
        _Pragma("unroll") \
        for (int j = 0; j < 4; j++) { \
            CPASYNC(d + M_AH * MATS * 2 + j * 16, gAh + ko + j * 8); \
            CPASYNC(d + M_BH * MATS * 2 + j * 16, gBh + ko + j * 8); \
            if (SPLITS >= 2) { \
                CPASYNC(d + M_AL * MATS * 2 + j * 16, gAl + ko + j * 8); \
                CPASYNC(d + M_BL * MATS * 2 + j * 16, gBl + ko + j * 8); \
            } \
        } }

    float acc[2][8][4];
#pragma unroll
    for (int i = 0; i < 2; i++)
#pragma unroll
        for (int j = 0; j < 8; j++)
#pragma unroll
            for (int k = 0; k < 4; k++) acc[i][j][k] = 0.0f;

    LOADCHUNK(0, 0);
    asm volatile("cp.async.commit_group;" ::: "memory");

    const uint32_t a_row_off =
        (uint32_t)((wm * 32 + (lane & 15)) * SROW) * 2 + (uint32_t)((lane >> 4) * 16);
    const int bn = wn * 64 + (lane & 7) + ((lane >> 4) << 3);
    const uint32_t b_row_off =
        (uint32_t)(bn * SROW) * 2 + (uint32_t)(((lane >> 3) & 1) * 16);

    for (int c = 0; c < 8; c++) {
        if (c < 7) {
            LOADCHUNK(c + 1, (c + 1) & 1);
            asm volatile("cp.async.commit_group;" ::: "memory");
            asm volatile("cp.async.wait_group 1;" ::: "memory");
        } else {
            asm volatile("cp.async.wait_group 0;" ::: "memory");
        }
        __syncthreads();

        const uint32_t base = sb + (uint32_t)(c & 1) * BUFB;
#pragma unroll
        for (int kk = 0; kk < 4; kk++) {
            const uint32_t aH = base + M_AH * MATS * 2 + a_row_off + kk * 32;
            const uint32_t aL = base + M_AL * MATS * 2 + a_row_off + kk * 32;
            uint32_t ah0[4], ah1[4], al0[4], al1[4];
            LDSM4(ah0, aH);
            LDSM4(ah1, aH + 16 * SROW * 2);
            if (SPLITS >= 2) {
                LDSM4(al0, aL);
                LDSM4(al1, aL + 16 * SROW * 2);
            }

            const uint32_t bH = base + M_BH * MATS * 2 + b_row_off + kk * 32;
            const uint32_t bL = base + M_BL * MATS * 2 + b_row_off + kk * 32;
#pragma unroll
            for (int jp = 0; jp < 4; jp++) {
                uint32_t bh[4], bl[4];
                LDSM4(bh, bH + jp * 16 * SROW * 2);
                if (SPLITS >= 3) LDSM4(bl, bL + jp * 16 * SROW * 2);

                MMA(acc[0][2 * jp],     ah0, bh[0], bh[1]);
                MMA(acc[1][2 * jp],     ah1, bh[0], bh[1]);
                MMA(acc[0][2 * jp + 1], ah0, bh[2], bh[3]);
                MMA(acc[1][2 * jp + 1], ah1, bh[2], bh[3]);
                if (SPLITS >= 2) {
                    MMA(acc[0][2 * jp],     al0, bh[0], bh[1]);
                    MMA(acc[1][2 * jp],     al1, bh[0], bh[1]);
                    MMA(acc[0][2 * jp + 1], al0, bh[2], bh[3]);
                    MMA(acc[1][2 * jp + 1], al1, bh[2], bh[3]);
                }
                if (SPLITS >= 3) {
                    MMA(acc[0][2 * jp],     ah0, bl[0], bl[1]);
                    MMA(acc[1][2 * jp],     ah1, bl[0], bl[1]);
                    MMA(acc[0][2 * jp + 1], ah0, bl[2], bl[3]);
                    MMA(acc[1][2 * jp + 1], ah1, bl[2], bl[3]);
                }
            }
        }
        __syncthreads();
    }

    const int r0 = m0 + wm * 32 + (lane >> 2);
    const int cb = ncol0 + wn * 64 + (lane & 3) * 2;
#pragma unroll
    for (int mi = 0; mi < 2; mi++) {
        const int r = r0 + mi * 16;
#pragma unroll
        for (int ni = 0; ni < 8; ni++) {
            const int cg = cb + ni * 8;
            *(float2*)&C[(size_t)r * 512 + cg] =
                make_float2(acc[mi][ni][0], acc[mi][ni][1]);
            *(float2*)&C[(size_t)(r + 8) * 512 + cg] =
                make_float2(acc[mi][ni][2], acc[mi][ni][3]);
        }
    }
}

// ---------------------------------------------------------------------------
// Collapse: masked softmax row = {-inf p<q, s_qq/8 at p=q, 0 p>q}
//   => z[q] = a_q*v[q] + c_q*suffix_{p>q} v[p]   (exact)
// ---------------------------------------------------------------------------
__global__ __launch_bounds__(256) void attn_stats()
{
    int t = blockIdx.x * 256 + threadIdx.x;   // 0..32767
    int m = t >> 3;
    int h = t & 7;
    const float4* qv = (const float4*)(g_Q + (size_t)m * DMODEL + h * DH);
    const float4* kv = (const float4*)(g_K + (size_t)m * DMODEL + h * DH);
    float s = 0.0f;
#pragma unroll
    for (int i = 0; i < 16; i++) {
        float4 a = qv[i], c = kv[i];
        s += a.x * c.x + a.y * c.y + a.z * c.z + a.w * c.w;
    }
    int b = m >> 11, q = m & 2047;
    float sd = s * 0.125f;
    int cnt = SEQ - 1 - q;
    float mx = (cnt > 0) ? fmaxf(sd, 0.0f) : sd;
    float ed = expf(sd - mx);
    float eo = (cnt > 0) ? expf(-mx) : 0.0f;
    float Z = ed + (float)cnt * eo;
    g_sa[(b * 8 + h) * SEQ + q] = ed / Z;
    g_sc[(b * 8 + h) * SEQ + q] = eo / Z;
}

// 64 chunks of 32 rows per (b,h). grid (16,16) x 256 thr.
__global__ __launch_bounds__(256) void v_chunksum()
{
    int bh = blockIdx.y;
    int chunk = blockIdx.x * 4 + (threadIdx.x >> 6);
    int dh = threadIdx.x & 63;
    int b = bh >> 3, h = bh & 7;
    const float* base = g_V + (size_t)(b * SEQ + chunk * 32) * DMODEL + h * DH + dh;
    float s = 0.0f;
#pragma unroll 8
    for (int i = 0; i < 32; i++) s += base[(size_t)i * DMODEL];
    g_cs[(bh * 64 + chunk) * 64 + dh] = s;
}

__global__ __launch_bounds__(256) void v_scan()
{
    int bh = blockIdx.y;
    int chunk = blockIdx.x * 4 + (threadIdx.x >> 6);
    int dh = threadIdx.x & 63;
    int b = bh >> 3, h = bh & 7;

    float run = 0.0f;
    const float* cs = g_cs + (size_t)bh * 64 * 64 + dh;
    for (int c2 = chunk + 1; c2 < 64; c2++)
        run += cs[(size_t)c2 * 64];

    const float* sa = g_sa + bh * SEQ;
    const float* sc = g_sc + bh * SEQ;
    const int q0 = chunk * 32;
#pragma unroll 4
    for (int i = 31; i >= 0; i--) {
        int q = q0 + i;
        size_t row = (size_t)(b * SEQ + q) * DMODEL + h * DH + dh;
        float v = g_V[row];
        float z = sa[q] * v + sc[q] * run;
        __half zh = __float2half_rn(z);
        g_zh[row] = zh;
        g_zl[row] = __float2half_rn(z - __half2float(zh));
        run += v;
    }
}

// ---------------------------------------------------------------------------
extern "C" void kernel_launch(void* const* d_in, const int* in_sizes, int n_in,
                              void* d_out, int out_size)
{
    const float* x  = (const float*)d_in[0];
    const float* WQ = (const float*)d_in[1];
    const float* WK = (const float*)d_in[2];
    const float* WV = (const float*)d_in[3];
    const float* WO = (const float*)d_in[4];
    float* out = (float*)d_out;

    const int SMEM1 = 2 * 2 * MATS * 2;   // 73728 B
    const int SMEM3 = 2 * 4 * MATS * 2;   // 147456 B
    cudaFuncSetAttribute(gemm_mma<1>, cudaFuncAttributeMaxDynamicSharedMemorySize,
                         SMEM1);
    cudaFuncSetAttribute(gemm_mma<3>, cudaFuncAttributeMaxDynamicSharedMemorySize,
                         SMEM3);

    __half *xh, *xl, *wh, *wl, *oh, *ol, *zh, *zl;
    float *gq, *gk, *gv;
    cudaGetSymbolAddress((void**)&xh, g_xh);
    cudaGetSymbolAddress((void**)&xl, g_xl);
    cudaGetSymbolAddress((void**)&wh, g_wh);
    cudaGetSymbolAddress((void**)&wl, g_wl);
    cudaGetSymbolAddress((void**)&oh, g_oh);
    cudaGetSymbolAddress((void**)&ol, g_ol);
    cudaGetSymbolAddress((void**)&zh, g_zh);
    cudaGetSymbolAddress((void**)&zl, g_zl);
    cudaGetSymbolAddress((void**)&gq, g_Q);
    cudaGetSymbolAddress((void**)&gk, g_K);
    cudaGetSymbolAddress((void**)&gv, g_V);

    convert_all<<<3072, 256>>>(x, WQ, WK, WV, WO);

    // Q + K fused (plain fp16): N = 1024
    dim3 gqk(8, 32);
    gemm_mma<1><<<gqk, 256, SMEM1>>>(xh, xl, wh, wl, gq, gk, gk);

    // V (fp16x3): N = 512, weights rows 1024..1535
    dim3 gv512(4, 32);
    gemm_mma<3><<<gv512, 256, SMEM3>>>(xh, xl, wh + 1024 * 512, wl + 1024 * 512,
                                       gv, gv, gv);

    attn_stats<<<128, 256>>>();
    v_chunksum<<<dim3(16, 16), 256>>>();
    v_scan<<<dim3(16, 16), 256>>>();

    // Output projection (fp16x3): N = 512
    gemm_mma<3><<<gv512, 256, SMEM3>>>(zh, zl, oh, ol, out, out, out);
}

// round 6
// speedup vs baseline: 3.5334x; 1.1959x over previous
#include <cuda_runtime.h>
#include <cuda_fp16.h>
#include <math.h>
#include <stdint.h>

#define SEQ     2048
#define DMODEL  512
#define NH      8
#define DH      64
#define BATCH   2
#define MTOT    4096

// ---------------- scratch (__device__ globals, allocation-free) -------------
__device__ __half g_xh[MTOT * DMODEL];
__device__ __half g_xl[MTOT * DMODEL];
__device__ __half g_wh[3 * DMODEL * DMODEL];   // [Wq;Wk;Wv] rows 0..1535 (hi)
__device__ __half g_wl[3 * DMODEL * DMODEL];   // lo used only for Wv range
__device__ __half g_oh[DMODEL * DMODEL];
__device__ __half g_ol[DMODEL * DMODEL];
__device__ __half g_zh[MTOT * DMODEL];
__device__ __half g_zl[MTOT * DMODEL];
__device__ float  g_V[MTOT * DMODEL];
__device__ float  g_sa[16 * SEQ];
__device__ float  g_sc[16 * SEQ];
__device__ float  g_cs[16 * 64 * 64];   // per-(bh, chunk32, dh) V column sums

// ---------------------------------------------------------------------------
__device__ __forceinline__ uint32_t smem_u32(const void* p) {
    uint32_t a;
    asm("{ .reg .u64 t; cvta.to.shared.u64 t, %1; cvt.u32.u64 %0, t; }"
        : "=r"(a) : "l"(p));
    return a;
}

#define CPASYNC(d, s) \
    asm volatile("cp.async.cg.shared.global [%0], [%1], 16;" \
                 :: "r"(d), "l"(s) : "memory")

#define LDSM4(r, a) \
    asm volatile("ldmatrix.sync.aligned.m8n8.x4.shared.b16 {%0,%1,%2,%3}, [%4];" \
                 : "=r"((r)[0]), "=r"((r)[1]), "=r"((r)[2]), "=r"((r)[3]) \
                 : "r"(a))

#define MMA(d, a, b0, b1) \
    asm volatile("mma.sync.aligned.m16n8k16.row.col.f32.f16.f16.f32 " \
                 "{%0,%1,%2,%3},{%4,%5,%6,%7},{%8,%9},{%0,%1,%2,%3};" \
                 : "+f"((d)[0]), "+f"((d)[1]), "+f"((d)[2]), "+f"((d)[3]) \
                 : "r"((a)[0]), "r"((a)[1]), "r"((a)[2]), "r"((a)[3]), \
                   "r"(b0), "r"(b1))

#define SROW 72                       // padded row in halves (144 B)
#define MATS (128 * SROW)             // halves per matrix tile

// ---------------------------------------------------------------------------
// fp32 -> fp16 hi/lo conversion (lo skipped for Wq/Wk)
// ---------------------------------------------------------------------------
__global__ __launch_bounds__(256) void convert_all(
    const float* __restrict__ x,  const float* __restrict__ wq,
    const float* __restrict__ wk, const float* __restrict__ wv,
    const float* __restrict__ wo)
{
    int t = blockIdx.x * 256 + threadIdx.x;       // float4 index, 786432 total
    const float* src;
    __half *dh, *dl;
    int idx;
    bool wantLo = true;
    if (t < 524288)      { src = x;  dh = g_xh;          dl = g_xl;          idx = t; }
    else if (t < 589824) { src = wq; dh = g_wh;          dl = g_wl;          idx = t - 524288; wantLo = false; }
    else if (t < 655360) { src = wk; dh = g_wh + 262144; dl = g_wl + 262144; idx = t - 589824; wantLo = false; }
    else if (t < 720896) { src = wv; dh = g_wh + 524288; dl = g_wl + 524288; idx = t - 655360; }
    else                 { src = wo; dh = g_oh;          dl = g_ol;          idx = t - 720896; }

    float4 v = ((const float4*)src)[idx];
    __half h0 = __float2half_rn(v.x), h1 = __float2half_rn(v.y);
    __half h2 = __float2half_rn(v.z), h3 = __float2half_rn(v.w);
    __half2* ph = (__half2*)(dh + idx * 4);
    ph[0] = __halves2half2(h0, h1); ph[1] = __halves2half2(h2, h3);
    if (wantLo) {
        __half l0 = __float2half_rn(v.x - __half2float(h0));
        __half l1 = __float2half_rn(v.y - __half2float(h1));
        __half l2 = __float2half_rn(v.z - __half2float(h2));
        __half l3 = __float2half_rn(v.w - __half2float(h3));
        __half2* pl = (__half2*)(dl + idx * 4);
        pl[0] = __halves2half2(l0, l1); pl[1] = __halves2half2(l2, l3);
    }
}

// ---------------------------------------------------------------------------
// Fused QK-diagonal GEMM: computes s[m,h] = (x W_Q^T)[m,hcols] . (x W_K^T)[m,hcols]
// directly in registers; no Q/K materialization. Writes softmax weights sa/sc.
// CTA 128 rows x 128 head-cols (= 2 heads), plain fp16, 3 smem mats (A,BQ,BK).
// ---------------------------------------------------------------------------
__global__ __launch_bounds__(256) void gemm_qk_diag(
    const __half* __restrict__ Ah,
    const __half* __restrict__ Wq,   // hi, rows 0..511
    const __half* __restrict__ Wk)   // hi, rows 0..511
{
    constexpr uint32_t BUFB = 3u * MATS * 2;   // bytes per buffer

    extern __shared__ __half sm[];
    const uint32_t sb = smem_u32(sm);
    const int tid = threadIdx.x;
    const int lane = tid & 31, wid = tid >> 5;
    const int wm = wid & 3, wn = wid >> 2;
    const int n0 = blockIdx.x * 128, m0 = blockIdx.y * 128;

    const int lr = tid >> 1, lp = tid & 1;
    const __half* gA = Ah + (size_t)(m0 + lr) * 512 + lp * 32;
    const __half* gQ = Wq + (size_t)(n0 + lr) * 512 + lp * 32;
    const __half* gK = Wk + (size_t)(n0 + lr) * 512 + lp * 32;
    const uint32_t dst0 = sb + (uint32_t)(lr * SROW + lp * 32) * 2;

#define LOADCHUNK_QK(c, b) { \
        const uint32_t d = dst0 + (uint32_t)(b) * BUFB; \
        const int ko = (c) * 64; \
        _Pragma("unroll") \
        for (int j = 0; j < 4; j++) { \
            CPASYNC(d + 0 * MATS * 2 + j * 16, gA + ko + j * 8); \
            CPASYNC(d + 1 * MATS * 2 + j * 16, gQ + ko + j * 8); \
            CPASYNC(d + 2 * MATS * 2 + j * 16, gK + ko + j * 8); \
        } }

    float aq[2][8][4], ak[2][8][4];
#pragma unroll
    for (int i = 0; i < 2; i++)
#pragma unroll
        for (int j = 0; j < 8; j++)
#pragma unroll
            for (int k = 0; k < 4; k++) { aq[i][j][k] = 0.0f; ak[i][j][k] = 0.0f; }

    LOADCHUNK_QK(0, 0);
    asm volatile("cp.async.commit_group;" ::: "memory");

    const uint32_t a_row_off =
        (uint32_t)((wm * 32 + (lane & 15)) * SROW) * 2 + (uint32_t)((lane >> 4) * 16);
    const int bn = wn * 64 + (lane & 7) + ((lane >> 4) << 3);
    const uint32_t b_row_off =
        (uint32_t)(bn * SROW) * 2 + (uint32_t)(((lane >> 3) & 1) * 16);

    for (int c = 0; c < 8; c++) {
        if (c < 7) {
            LOADCHUNK_QK(c + 1, (c + 1) & 1);
            asm volatile("cp.async.commit_group;" ::: "memory");
            asm volatile("cp.async.wait_group 1;" ::: "memory");
        } else {
            asm volatile("cp.async.wait_group 0;" ::: "memory");
        }
        __syncthreads();

        const uint32_t base = sb + (uint32_t)(c & 1) * BUFB;
#pragma unroll
        for (int kk = 0; kk < 4; kk++) {
            const uint32_t aA = base + a_row_off + kk * 32;
            uint32_t a0[4], a1[4];
            LDSM4(a0, aA);
            LDSM4(a1, aA + 16 * SROW * 2);

            const uint32_t bQ = base + 1 * MATS * 2 + b_row_off + kk * 32;
            const uint32_t bK = base + 2 * MATS * 2 + b_row_off + kk * 32;
#pragma unroll
            for (int jp = 0; jp < 4; jp++) {
                uint32_t bq[4], bk[4];
                LDSM4(bq, bQ + jp * 16 * SROW * 2);
                LDSM4(bk, bK + jp * 16 * SROW * 2);
                MMA(aq[0][2 * jp],     a0, bq[0], bq[1]);
                MMA(aq[1][2 * jp],     a1, bq[0], bq[1]);
                MMA(aq[0][2 * jp + 1], a0, bq[2], bq[3]);
                MMA(aq[1][2 * jp + 1], a1, bq[2], bq[3]);
                MMA(ak[0][2 * jp],     a0, bk[0], bk[1]);
                MMA(ak[1][2 * jp],     a1, bk[0], bk[1]);
                MMA(ak[0][2 * jp + 1], a0, bk[2], bk[3]);
                MMA(ak[1][2 * jp + 1], a1, bk[2], bk[3]);
            }
        }
        __syncthreads();
    }

    // Epilogue: per-row head dot (this warp's 64 cols = exactly one head)
    const int h = blockIdx.x * 2 + wn;
#pragma unroll
    for (int j = 0; j < 4; j++) {
        const int mi = j >> 1, o = (j & 1) * 2;
        float p = 0.0f;
#pragma unroll
        for (int ni = 0; ni < 8; ni++)
            p += aq[mi][ni][o] * ak[mi][ni][o]
               + aq[mi][ni][o + 1] * ak[mi][ni][o + 1];
        p += __shfl_xor_sync(0xFFFFFFFF, p, 1);
        p += __shfl_xor_sync(0xFFFFFFFF, p, 2);
        if ((lane & 3) == 0) {
            const int m = m0 + wm * 32 + (lane >> 2) + (j >> 1) * 16 + (j & 1) * 8;
            const int b = m >> 11, q = m & 2047;
            float sd = p * 0.125f;
            int cnt = SEQ - 1 - q;
            float mx = (cnt > 0) ? fmaxf(sd, 0.0f) : sd;
            float ed = expf(sd - mx);
            float eo = (cnt > 0) ? expf(-mx) : 0.0f;
            float Z = ed + (float)cnt * eo;
            g_sa[(b * 8 + h) * SEQ + q] = ed / Z;
            g_sc[(b * 8 + h) * SEQ + q] = eo / Z;
        }
    }
}

// ---------------------------------------------------------------------------
// HMMA fp16x3 GEMM (hi/lo compensated): C = A.B^T
// ---------------------------------------------------------------------------
__global__ __launch_bounds__(256) void gemm_mma3(
    const __half* __restrict__ Ah, const __half* __restrict__ Al,
    const __half* __restrict__ Bh, const __half* __restrict__ Bl,
    float* __restrict__ C)
{
    constexpr uint32_t BUFB = 4u * MATS * 2;

    extern __shared__ __half sm[];
    const uint32_t sb = smem_u32(sm);
    const int tid = threadIdx.x;
    const int lane = tid & 31, wid = tid >> 5;
    const int wm = wid & 3, wn = wid >> 2;
    const int n0 = blockIdx.x * 128, m0 = blockIdx.y * 128;

    const int lr = tid >> 1, lp = tid & 1;
    const __half* gAh = Ah + (size_t)(m0 + lr) * 512 + lp * 32;
    const __half* gAl = Al + (size_t)(m0 + lr) * 512 + lp * 32;
    const __half* gBh = Bh + (size_t)(n0 + lr) * 512 + lp * 32;
    const __half* gBl = Bl + (size_t)(n0 + lr) * 512 + lp * 32;
    const uint32_t dst0 = sb + (uint32_t)(lr * SROW + lp * 32) * 2;

#define LOADCHUNK3(c, b) { \
        const uint32_t d = dst0 + (uint32_t)(b) * BUFB; \
        const int ko = (c) * 64; \
        _Pragma("unroll") \
        for (int j = 0; j < 4; j++) { \
            CPASYNC(d + 0 * MATS * 2 + j * 16, gAh + ko + j * 8); \
            CPASYNC(d + 1 * MATS * 2 + j * 16, gAl + ko + j * 8); \
            CPASYNC(d + 2 * MATS * 2 + j * 16, gBh + ko + j * 8); \
            CPASYNC(d + 3 * MATS * 2 + j * 16, gBl + ko + j * 8); \
        } }

    float acc[2][8][4];
#pragma unroll
    for (int i = 0; i < 2; i++)
#pragma unroll
        for (int j = 0; j < 8; j++)
#pragma unroll
            for (int k = 0; k < 4; k++) acc[i][j][k] = 0.0f;

    LOADCHUNK3(0, 0);
    asm volatile("cp.async.commit_group;" ::: "memory");

    const uint32_t a_row_off =
        (uint32_t)((wm * 32 + (lane & 15)) * SROW) * 2 + (uint32_t)((lane >> 4) * 16);
    const int bn = wn * 64 + (lane & 7) + ((lane >> 4) << 3);
    const uint32_t b_row_off =
        (uint32_t)(bn * SROW) * 2 + (uint32_t)(((lane >> 3) & 1) * 16);

    for (int c = 0; c < 8; c++) {
        if (c < 7) {
            LOADCHUNK3(c + 1, (c + 1) & 1);
            asm volatile("cp.async.commit_group;" ::: "memory");
            asm volatile("cp.async.wait_group 1;" ::: "memory");
        } else {
            asm volatile("cp.async.wait_group 0;" ::: "memory");
        }
        __syncthreads();

        const uint32_t base = sb + (uint32_t)(c & 1) * BUFB;
#pragma unroll
        for (int kk = 0; kk < 4; kk++) {
            const uint32_t aH = base + a_row_off + kk * 32;
            const uint32_t aL = aH + MATS * 2;
            uint32_t ah0[4], ah1[4], al0[4], al1[4];
            LDSM4(ah0, aH);
            LDSM4(ah1, aH + 16 * SROW * 2);
            LDSM4(al0, aL);
            LDSM4(al1, aL + 16 * SROW * 2);

            const uint32_t bH = base + 2 * MATS * 2 + b_row_off + kk * 32;
            const uint32_t bL = bH + MATS * 2;
#pragma unroll
            for (int jp = 0; jp < 4; jp++) {
                uint32_t bh[4], bl[4];
                LDSM4(bh, bH + jp * 16 * SROW * 2);
                LDSM4(bl, bL + jp * 16 * SROW * 2);
                MMA(acc[0][2 * jp],     ah0, bh[0], bh[1]);
                MMA(acc[1][2 * jp],     ah1, bh[0], bh[1]);
                MMA(acc[0][2 * jp + 1], ah0, bh[2], bh[3]);
                MMA(acc[1][2 * jp + 1], ah1, bh[2], bh[3]);
                MMA(acc[0][2 * jp],     al0, bh[0], bh[1]);
                MMA(acc[1][2 * jp],     al1, bh[0], bh[1]);
                MMA(acc[0][2 * jp + 1], al0, bh[2], bh[3]);
                MMA(acc[1][2 * jp + 1], al1, bh[2], bh[3]);
                MMA(acc[0][2 * jp],     ah0, bl[0], bl[1]);
                MMA(acc[1][2 * jp],     ah1, bl[0], bl[1]);
                MMA(acc[0][2 * jp + 1], ah0, bl[2], bl[3]);
                MMA(acc[1][2 * jp + 1], ah1, bl[2], bl[3]);
            }
        }
        __syncthreads();
    }

    const int r0 = m0 + wm * 32 + (lane >> 2);
    const int cb = n0 + wn * 64 + (lane & 3) * 2;
#pragma unroll
    for (int mi = 0; mi < 2; mi++) {
        const int r = r0 + mi * 16;
#pragma unroll
        for (int ni = 0; ni < 8; ni++) {
            const int cg = cb + ni * 8;
            *(float2*)&C[(size_t)r * 512 + cg] =
                make_float2(acc[mi][ni][0], acc[mi][ni][1]);
            *(float2*)&C[(size_t)(r + 8) * 512 + cg] =
                make_float2(acc[mi][ni][2], acc[mi][ni][3]);
        }
    }
}

// ---------------------------------------------------------------------------
// Collapse: z[q] = a_q*v[q] + c_q*suffix_{p>q} v[p]
// ---------------------------------------------------------------------------
__global__ __launch_bounds__(256) void v_chunksum()
{
    int bh = blockIdx.y;
    int chunk = blockIdx.x * 4 + (threadIdx.x >> 6);
    int dh = threadIdx.x & 63;
    int b = bh >> 3, h = bh & 7;
    const float* base = g_V + (size_t)(b * SEQ + chunk * 32) * DMODEL + h * DH + dh;
    float s = 0.0f;
#pragma unroll 8
    for (int i = 0; i < 32; i++) s += base[(size_t)i * DMODEL];
    g_cs[(bh * 64 + chunk) * 64 + dh] = s;
}

__global__ __launch_bounds__(256) void v_scan()
{
    int bh = blockIdx.y;
    int chunk = blockIdx.x * 4 + (threadIdx.x >> 6);
    int dh = threadIdx.x & 63;
    int b = bh >> 3, h = bh & 7;

    float run = 0.0f;
    const float* cs = g_cs + (size_t)bh * 64 * 64 + dh;
    for (int c2 = chunk + 1; c2 < 64; c2++)
        run += cs[(size_t)c2 * 64];

    const float* sa = g_sa + bh * SEQ;
    const float* sc = g_sc + bh * SEQ;
    const int q0 = chunk * 32;
#pragma unroll 4
    for (int i = 31; i >= 0; i--) {
        int q = q0 + i;
        size_t row = (size_t)(b * SEQ + q) * DMODEL + h * DH + dh;
        float v = g_V[row];
        float z = sa[q] * v + sc[q] * run;
        __half zh = __float2half_rn(z);
        g_zh[row] = zh;
        g_zl[row] = __float2half_rn(z - __half2float(zh));
        run += v;
    }
}

// ---------------------------------------------------------------------------
extern "C" void kernel_launch(void* const* d_in, const int* in_sizes, int n_in,
                              void* d_out, int out_size)
{
    const float* x  = (const float*)d_in[0];
    const float* WQ = (const float*)d_in[1];
    const float* WK = (const float*)d_in[2];
    const float* WV = (const float*)d_in[3];
    const float* WO = (const float*)d_in[4];
    float* out = (float*)d_out;

    const int SMEMQK = 2 * 3 * MATS * 2;   // 110592 B
    const int SMEM3  = 2 * 4 * MATS * 2;   // 147456 B
    cudaFuncSetAttribute(gemm_qk_diag, cudaFuncAttributeMaxDynamicSharedMemorySize,
                         SMEMQK);
    cudaFuncSetAttribute(gemm_mma3, cudaFuncAttributeMaxDynamicSharedMemorySize,
                         SMEM3);

    __half *xh, *xl, *wh, *wl, *oh, *ol, *zh, *zl;
    float *gv;
    cudaGetSymbolAddress((void**)&xh, g_xh);
    cudaGetSymbolAddress((void**)&xl, g_xl);
    cudaGetSymbolAddress((void**)&wh, g_wh);
    cudaGetSymbolAddress((void**)&wl, g_wl);
    cudaGetSymbolAddress((void**)&oh, g_oh);
    cudaGetSymbolAddress((void**)&ol, g_ol);
    cudaGetSymbolAddress((void**)&zh, g_zh);
    cudaGetSymbolAddress((void**)&zl, g_zl);
    cudaGetSymbolAddress((void**)&gv, g_V);

    convert_all<<<3072, 256>>>(x, WQ, WK, WV, WO);

    // Fused QK-diag: writes g_sa/g_sc directly (no Q/K materialization)
    dim3 gqk(4, 32);
    gemm_qk_diag<<<gqk, 256, SMEMQK>>>(xh, wh, wh + 512 * 512);

    // V (fp16x3): weights rows 1024..1535
    dim3 g512(4, 32);
    gemm_mma3<<<g512, 256, SMEM3>>>(xh, xl, wh + 1024 * 512, wl + 1024 * 512, gv);

    v_chunksum<<<dim3(16, 16), 256>>>();
    v_scan<<<dim3(16, 16), 256>>>();

    // Output projection (fp16x3)
    gemm_mma3<<<g512, 256, SMEM3>>>(zh, zl, oh, ol, out);
}